// round 9
// baseline (speedup 1.0000x reference)
#include <cuda_runtime.h>

// x: (B=16, L=8192, F=512) float32, contiguous.
// y[b,t,:] = x[b,t+1,:] - x[b,t,:]   for t < L-1
// y[b,L-1,:] = x[b,L-1,:] - x[b,L-2,:]
//
// Register-reuse scheme: each thread owns one float4 feature column and
// ROWS=8 consecutive time steps. Loads ROWS+1=9 float4 (vs 16 in the
// non-reusing version), computes 8 diffs in registers, stores 8.
// Tile rows never straddle a sequence boundary (8192 % 8 == 0).
// For the last tile of a sequence, y[L-1] repeats d[ROWS-2] — register copy,
// no extra load (also avoids OOB at the end of the tensor).

static constexpr int F4    = 512 / 4;  // 128 float4 per row
static constexpr int L     = 8192;
static constexpr int ROWS  = 8;        // time steps per tile
static constexpr int TPB   = 128;      // one thread per float4 column

__global__ void __launch_bounds__(TPB)
diff1d_kernel(const float4* __restrict__ x, float4* __restrict__ y)
{
    int tile = blockIdx.x;                   // 16*8192/8 = 16384 tiles
    int c    = threadIdx.x;                  // feature column 0..127
    int base = tile * (ROWS * F4) + c;       // max 16.7M, fits int
    int t0   = (tile * ROWS) & (L - 1);
    bool lastTile = (t0 == L - ROWS);        // block-uniform

    float4 a[ROWS + 1];

    // Front-batched loads: 8 unconditional + 1 predicated (block-uniform branch)
    #pragma unroll
    for (int i = 0; i < ROWS; i++)
        a[i] = x[base + i * F4];
    a[ROWS] = lastTile ? a[ROWS - 1] : x[base + ROWS * F4];

    float4 d[ROWS];
    #pragma unroll
    for (int i = 0; i < ROWS; i++) {
        d[i].x = a[i + 1].x - a[i].x;
        d[i].y = a[i + 1].y - a[i].y;
        d[i].z = a[i + 1].z - a[i].z;
        d[i].w = a[i + 1].w - a[i].w;
    }
    if (lastTile)
        d[ROWS - 1] = d[ROWS - 2];           // y[L-1] = repeated last diff

    #pragma unroll
    for (int i = 0; i < ROWS; i++)
        y[base + i * F4] = d[i];
}

extern "C" void kernel_launch(void* const* d_in, const int* in_sizes, int n_in,
                              void* d_out, int out_size)
{
    const float4* x = (const float4*)d_in[0];
    float4* y = (float4*)d_out;

    int n4     = out_size / 4;               // 16,777,216 float4
    int blocks = n4 / (ROWS * F4);           // 16384, exact
    diff1d_kernel<<<blocks, TPB>>>(x, y);
}